// round 11
// baseline (speedup 1.0000x reference)
#include <cuda_runtime.h>
#include <cuda_bf16.h>
#include <math.h>

// Problem constants (match reference)
#define BB 16
#define KK 64
#define HH 160
#define WW 160
#define EPSV 1e-5f

// Scratch:
//  g_P[b,k,i]  = {cr0, g, g^4, g^64}: cr0 = den*exp(ay*dy^2 - c*dy*x) (row
//                factor at j=0), g = exp(c*dy). g^4/g^64 stored via DIRECT
//                expf (no error amplification through squaring chains).
//  g_Ex[b,k,j] = exp(ax*dx^2) (pure column factor).
//  g_Inv[b,i,j]= 1/(sum_k value + eps).
__device__ float4 g_P[BB * KK * HH];
__device__ float  g_Ex[BB * KK * WW];
__device__ float  g_Inv[BB * HH * WW];

__global__ __launch_bounds__(256)
void precompute_kernel(const float* __restrict__ kp,
                       const float* __restrict__ psx,
                       const float* __restrict__ psy,
                       const float* __restrict__ prho)
{
    int idx = blockIdx.x * 256 + threadIdx.x;   // 0 .. 163839 (= 1024*160)
    int bk  = idx / 160;
    int t   = idx - bk * 160;

    float sx  = psx[0];
    float sy  = psy[0];
    float rho = prho[0];

    float om   = 1.0f - rho * rho;
    float den  = 1.0f / (2.0f * 3.14159265358979323846f * sx * sy * sqrtf(om));
    float num1 = -1.0f / (2.0f * om);
    float ay   = num1 / (sy * sy);
    float ax   = num1 / (sx * sx);
    float c    = rho / (om * sx * sy);

    float x = kp[bk * 2 + 0];
    float y = kp[bk * 2 + 1];

    float dy  = (float)t - y;
    float cdy = c * dy;
    float4 P;
    P.x = den * expf(ay * dy * dy - cdy * x);
    P.y = expf(cdy);
    P.z = expf(4.0f  * cdy);
    P.w = expf(64.0f * cdy);
    g_P[bk * HH + t] = P;

    float dx = (float)t - x;
    g_Ex[bk * WW + t] = expf(ax * dx * dx);
}

// Denominator: CTA = (b, itile of 8). One warp per i, loops all 64 k,
// accumulating in 5 registers. Lane l owns j = l + 32m (m=0..4): fully
// coalesced, no tail divergence. Ex/P rows are L1-cached across warps.
__global__ __launch_bounds__(256)
void denom_kernel()
{
    int it = blockIdx.x;               // 0..19
    int b  = blockIdx.y;               // 0..15
    int w  = threadIdx.x >> 5;
    int l  = threadIdx.x & 31;
    int i  = it * 8 + w;

    float acc0 = 0.f, acc1 = 0.f, acc2 = 0.f, acc3 = 0.f, acc4 = 0.f;

    const float4* Pp  = g_P  + b * KK * HH + i;    // + k*HH per k
    const float*  Exb = g_Ex + b * KK * WW + l;    // + k*WW per k

#pragma unroll 8
    for (int k = 0; k < KK; ++k) {
        float4 P = Pp[k * HH];
        const float* ex = Exb + k * WW;
        float e0 = ex[0], e1 = ex[32], e2 = ex[64], e3 = ex[96], e4 = ex[128];

        float g = P.y, g4 = P.z;
        float g2  = g  * g;
        float g8  = g4 * g4;
        float g16 = g8 * g8;
        float g32 = g16 * g16;
        float p = 1.0f;
        if (l & 1)  p *= g;
        if (l & 2)  p *= g2;
        if (l & 4)  p *= g4;
        if (l & 8)  p *= g8;
        if (l & 16) p *= g16;
        float crl = P.x * p;

        acc0 = fmaf(crl, e0, acc0); crl *= g32;
        acc1 = fmaf(crl, e1, acc1); crl *= g32;
        acc2 = fmaf(crl, e2, acc2); crl *= g32;
        acc3 = fmaf(crl, e3, acc3); crl *= g32;
        acc4 = fmaf(crl, e4, acc4);
    }

    float* invp = g_Inv + (b * HH + i) * WW + l;
    invp[0]   = 1.0f / (acc0 + EPSV);
    invp[32]  = 1.0f / (acc1 + EPSV);
    invp[64]  = 1.0f / (acc2 + EPSV);
    invp[96]  = 1.0f / (acc3 + EPSV);
    invp[128] = 1.0f / (acc4 + EPSV);
}

// Main kernel: CTA = (b, ktile 16, itile 16). Warp owns 2 i rows (inv held in
// 10 registers), loops 16 k. Ex/P L1-cached across the CTA's warps. Stores
// are coalesced STG.32 runs; output (105 MB) stays L2-resident.
__global__ __launch_bounds__(256)
void recon_out_kernel(float* __restrict__ out)
{
    int b  = blockIdx.x;               // 16
    int kt = blockIdx.y;               // 4
    int it = blockIdx.z;               // 10
    int w  = threadIdx.x >> 5;
    int l  = threadIdx.x & 31;
    int i0 = it * 16 + w * 2;

    const float* iva = g_Inv + (b * HH + i0) * WW + l;
    float ia0 = iva[0], ia1 = iva[32], ia2 = iva[64], ia3 = iva[96], ia4 = iva[128];
    const float* ivb = iva + WW;
    float ib0 = ivb[0], ib1 = ivb[32], ib2 = ivb[64], ib3 = ivb[96], ib4 = ivb[128];

    int kbase = b * KK + kt * 16;

#pragma unroll 4
    for (int kk = 0; kk < 16; ++kk) {
        int bk = kbase + kk;
        const float* ex = g_Ex + bk * WW + l;
        float e0 = ex[0], e1 = ex[32], e2 = ex[64], e3 = ex[96], e4 = ex[128];

        const float4* Pr = g_P + bk * HH;
        float* ob = out + ((size_t)bk * HH) * WW + l;

        // row i0
        {
            float4 P = Pr[i0];
            float g = P.y, g4 = P.z;
            float g2  = g  * g;
            float g8  = g4 * g4;
            float g16 = g8 * g8;
            float g32 = g16 * g16;
            float p = 1.0f;
            if (l & 1)  p *= g;
            if (l & 2)  p *= g2;
            if (l & 4)  p *= g4;
            if (l & 8)  p *= g8;
            if (l & 16) p *= g16;
            float crl = P.x * p;
            float* o = ob + (size_t)i0 * WW;
            o[0]   = crl * e0 * ia0; crl *= g32;
            o[32]  = crl * e1 * ia1; crl *= g32;
            o[64]  = crl * e2 * ia2; crl *= g32;
            o[96]  = crl * e3 * ia3; crl *= g32;
            o[128] = crl * e4 * ia4;
        }
        // row i0 + 1
        {
            float4 P = Pr[i0 + 1];
            float g = P.y, g4 = P.z;
            float g2  = g  * g;
            float g8  = g4 * g4;
            float g16 = g8 * g8;
            float g32 = g16 * g16;
            float p = 1.0f;
            if (l & 1)  p *= g;
            if (l & 2)  p *= g2;
            if (l & 4)  p *= g4;
            if (l & 8)  p *= g8;
            if (l & 16) p *= g16;
            float crl = P.x * p;
            float* o = ob + (size_t)(i0 + 1) * WW;
            o[0]   = crl * e0 * ib0; crl *= g32;
            o[32]  = crl * e1 * ib1; crl *= g32;
            o[64]  = crl * e2 * ib2; crl *= g32;
            o[96]  = crl * e3 * ib3; crl *= g32;
            o[128] = crl * e4 * ib4;
        }
    }
}

extern "C" void kernel_launch(void* const* d_in, const int* in_sizes, int n_in,
                              void* d_out, int out_size)
{
    const float* kp  = (const float*)d_in[0];  // keypoints [B,K,2]
    const float* sx  = (const float*)d_in[1];  // std_x (scalar)
    const float* sy  = (const float*)d_in[2];  // std_y (scalar)
    const float* rho = (const float*)d_in[3];  // correlation (scalar)
    // d_in[4] = DetectionMap: unused by the reference math (shape only).
    float* out = (float*)d_out;

    precompute_kernel<<<640, 256>>>(kp, sx, sy, rho);

    dim3 dgrid(20, BB);
    denom_kernel<<<dgrid, 256>>>();

    dim3 mgrid(BB, 4, 10);
    recon_out_kernel<<<mgrid, 256>>>(out);
}

// round 15
// speedup vs baseline: 1.1558x; 1.1558x over previous
#include <cuda_runtime.h>
#include <cuda_bf16.h>
#include <math.h>

// Problem constants (match reference)
#define BB 16
#define KK 64
#define HH 160
#define WW 160
#define EPSV 1e-5f

// Scratch:
//  g_P[b,k,i]  = {cr0, g, -, -}: cr0 = den*exp(ay*dy^2 - c*dy*x) (row factor
//                at j=0), g = exp(c*dy) (per-step cross multiplier in j).
//  g_Ex[b,k,j] = exp(ax*dx^2) (pure column factor).
//  g_Inv[b,i,j]= 1/(sum_k value + eps).
__device__ float4 g_P[BB * KK * HH];
__device__ float  g_Ex[BB * KK * WW];
__device__ float  g_Inv[BB * HH * WW];

__global__ __launch_bounds__(256)
void precompute_kernel(const float* __restrict__ kp,
                       const float* __restrict__ psx,
                       const float* __restrict__ psy,
                       const float* __restrict__ prho)
{
    int idx = blockIdx.x * 256 + threadIdx.x;   // 0 .. 163839
    int bk  = idx / 160;
    int t   = idx - bk * 160;

    float sx  = psx[0];
    float sy  = psy[0];
    float rho = prho[0];

    float om   = 1.0f - rho * rho;
    float den  = 1.0f / (2.0f * 3.14159265358979323846f * sx * sy * sqrtf(om));
    float num1 = -1.0f / (2.0f * om);
    float ay   = num1 / (sy * sy);
    float ax   = num1 / (sx * sx);
    float c    = rho / (om * sx * sy);

    float x = kp[bk * 2 + 0];
    float y = kp[bk * 2 + 1];

    float dy  = (float)t - y;
    float cdy = c * dy;
    float4 P;
    P.x = den * expf(ay * dy * dy - cdy * x);  // cr at j = 0
    P.y = expf(cdy);                           // per-step multiplier g
    P.z = 0.0f;
    P.w = 0.0f;
    g_P[bk * HH + t] = P;

    float dx = (float)t - x;
    g_Ex[bk * WW + t] = expf(ax * dx * dx);
}

// Binary powering: h^l for lane l in [0,32).
__device__ __forceinline__ float pow_lane(float h, float h2, float h4,
                                          float h8, float h16, int l)
{
    float p = 1.0f;
    if (l & 1)  p *= h;
    if (l & 2)  p *= h2;
    if (l & 4)  p *= h4;
    if (l & 8)  p *= h8;
    if (l & 16) p *= h16;
    return p;
}

// Denominator kernel (R9-measured version): CTA = (i, b). 8 warps; warp w
// sums k = 8w..8w+7 into per-warp partials, combined via 5 KB smem.
__global__ __launch_bounds__(256)
void denom_kernel()
{
    __shared__ float S[8][WW];

    int i = blockIdx.x;                // row 0..159
    int b = blockIdx.y;                // batch 0..15
    int w = threadIdx.x >> 5;
    int l = threadIdx.x & 31;

    float4 acc  = make_float4(0.f, 0.f, 0.f, 0.f);  // j = 4l .. 4l+3
    float4 acc2 = make_float4(0.f, 0.f, 0.f, 0.f);  // lanes<8: j = 128+4l ..

#pragma unroll
    for (int kk = 0; kk < 8; ++kk) {
        int bk = b * KK + w * 8 + kk;
        float4 P  = g_P[bk * HH + i];
        float cr0 = P.x, g = P.y;
        float g2 = g * g, g3 = g2 * g;
        float h  = g2 * g2;
        float h2 = h * h, h4 = h2 * h2, h8 = h4 * h4, h16 = h8 * h8;
        float p  = pow_lane(h, h2, h4, h8, h16, l);

        const float4* ex4 = reinterpret_cast<const float4*>(g_Ex + bk * WW);
        float4 e   = ex4[l];
        float  crl = cr0 * p;
        acc.x += crl * e.x;
        acc.y += crl * g  * e.y;
        acc.z += crl * g2 * e.z;
        acc.w += crl * g3 * e.w;

        if (l < 8) {
            float4 e2  = ex4[32 + l];
            float  crt = cr0 * (h16 * h16) * p;   // h^(32+l)
            acc2.x += crt * e2.x;
            acc2.y += crt * g  * e2.y;
            acc2.z += crt * g2 * e2.z;
            acc2.w += crt * g3 * e2.w;
        }
    }

    reinterpret_cast<float4*>(S[w])[l] = acc;
    if (l < 8)
        reinterpret_cast<float4*>(S[w])[32 + l] = acc2;
    __syncthreads();

    int t = threadIdx.x;
    if (t < WW) {
        float s = 0.0f;
#pragma unroll
        for (int ww = 0; ww < 8; ++ww) s += S[ww][t];
        g_Inv[(b * HH + i) * WW + t] = 1.0f / (s + EPSV);
    }
}

// Main kernel: CTA = (b, ktile of 8, iquarter of 40). 8 warps = 8 distinct k;
// each warp loops 40 i rows with float4 accesses (lane l -> j=4l..4l+3,
// lanes<8 also take j=128+4l..). All warps share each inv row via L1
// (one L2 miss, 7 L1 hits) -> inv L2 traffic drops 105 MB -> ~13 MB.
__global__ __launch_bounds__(256)
void recon_out_kernel(float* __restrict__ out)
{
    int b  = blockIdx.x;               // 16
    int kt = blockIdx.y;               // 8
    int iq = blockIdx.z;               // 4
    int w  = threadIdx.x >> 5;
    int l  = threadIdx.x & 31;
    int bk = b * KK + kt * 8 + w;

    const float4* ex4 = reinterpret_cast<const float4*>(g_Ex + bk * WW);
    float4 e  = ex4[l];
    float4 e2 = make_float4(0.f, 0.f, 0.f, 0.f);
    if (l < 8) e2 = ex4[32 + l];

    int i0 = iq * 40;

#pragma unroll 4
    for (int r = 0; r < 40; ++r) {
        int i = i0 + r;
        float4 P  = g_P[bk * HH + i];
        float cr0 = P.x, g = P.y;
        float g2 = g * g, g3 = g2 * g;
        float h  = g2 * g2;
        float h2 = h * h, h4 = h2 * h2, h8 = h4 * h4, h16 = h8 * h8;
        float p  = pow_lane(h, h2, h4, h8, h16, l);

        const float4* inv4 =
            reinterpret_cast<const float4*>(g_Inv + (b * HH + i) * WW);
        float4 iv  = inv4[l];
        float  crl = cr0 * p;

        float4 v;
        v.x = crl * e.x * iv.x;
        v.y = crl * g  * e.y * iv.y;
        v.z = crl * g2 * e.z * iv.z;
        v.w = crl * g3 * e.w * iv.w;

        float4* orow =
            reinterpret_cast<float4*>(out + ((size_t)bk * HH + i) * WW);
        orow[l] = v;

        if (l < 8) {
            float4 iv2 = inv4[32 + l];
            float  crt = cr0 * (h16 * h16) * p;   // h^(32+l)
            float4 v2;
            v2.x = crt * e2.x * iv2.x;
            v2.y = crt * g  * e2.y * iv2.y;
            v2.z = crt * g2 * e2.z * iv2.z;
            v2.w = crt * g3 * e2.w * iv2.w;
            orow[32 + l] = v2;
        }
    }
}

extern "C" void kernel_launch(void* const* d_in, const int* in_sizes, int n_in,
                              void* d_out, int out_size)
{
    const float* kp  = (const float*)d_in[0];  // keypoints [B,K,2]
    const float* sx  = (const float*)d_in[1];  // std_x (scalar)
    const float* sy  = (const float*)d_in[2];  // std_y (scalar)
    const float* rho = (const float*)d_in[3];  // correlation (scalar)
    // d_in[4] = DetectionMap: unused by the reference math (shape only).
    float* out = (float*)d_out;

    precompute_kernel<<<640, 256>>>(kp, sx, sy, rho);

    dim3 dgrid(HH, BB);
    denom_kernel<<<dgrid, 256>>>();

    dim3 mgrid(BB, 8, 4);
    recon_out_kernel<<<mgrid, 256>>>(out);
}